// round 2
// baseline (speedup 1.0000x reference)
#include <cuda_runtime.h>
#include <math.h>

#define FULL 0xffffffffu
#define WPB 8  // warps (matrices) per block

// One-sided (Hestenes) Jacobi eigensolver, one warp per 32x32 SPD matrix.
// Thread t owns column t of W (initially P, symmetric -> row t). Rotations
// orthogonalize column pairs; at convergence lambda_i = ||w_i||, u_i = w_i/||w_i||.
// Output X = U diag(log lambda) U^T reconstructed via shared memory.
__global__ __launch_bounds__(WPB * 32)
void logeig_kernel(const float* __restrict__ P, float* __restrict__ out, int nmat)
{
    __shared__ float sh[WPB][32 * 33 + 32];
    const int lane = threadIdx.x & 31;
    const int wib  = threadIdx.x >> 5;
    const int mat  = blockIdx.x * WPB + wib;
    if (mat >= nmat) return;

    // Load: P is symmetric, so row `lane` == column `lane`. 8x LDG.128, coalesced.
    float a[32];
    {
        const float4* p4 = reinterpret_cast<const float4*>(P + (size_t)mat * 1024 + lane * 32);
        #pragma unroll
        for (int k = 0; k < 8; k++) {
            float4 v = p4[k];
            a[4*k+0] = v.x; a[4*k+1] = v.y; a[4*k+2] = v.z; a[4*k+3] = v.w;
        }
    }

    // ---- One-sided Jacobi sweeps (tournament ordering, 31 rounds/sweep) ----
    for (int sweep = 0; sweep < 10; sweep++) {
        float maxoff = 0.0f;
        for (int r = 0; r < 31; r++) {
            // 1-factorization of K32: lanes i,j<31 pair iff i+j == r (mod 31);
            // the lane with 2i == r (mod 31) pairs with lane 31. (16 = 2^-1 mod 31)
            int partner;
            if (lane == 31) {
                partner = (16 * r) % 31;
            } else {
                int j = r - lane; if (j < 0) j += 31;
                partner = (j == lane) ? 31 : j;
            }

            // Fetch partner's column, compute dot + own norm (4-way ILP).
            float b[32];
            #pragma unroll
            for (int i = 0; i < 32; i++) b[i] = __shfl_sync(FULL, a[i], partner);

            float d0=0.f,d1=0.f,d2=0.f,d3=0.f, n0=0.f,n1=0.f,n2=0.f,n3=0.f;
            #pragma unroll
            for (int i = 0; i < 32; i += 4) {
                d0 = fmaf(a[i+0], b[i+0], d0); n0 = fmaf(a[i+0], a[i+0], n0);
                d1 = fmaf(a[i+1], b[i+1], d1); n1 = fmaf(a[i+1], a[i+1], n1);
                d2 = fmaf(a[i+2], b[i+2], d2); n2 = fmaf(a[i+2], a[i+2], n2);
                d3 = fmaf(a[i+3], b[i+3], d3); n3 = fmaf(a[i+3], a[i+3], n3);
            }
            // Both lanes of a pair compute bitwise-identical apq (same products,
            // same accumulation order) -> identical c,s without extra exchange.
            float apq  = (d0 + d1) + (d2 + d3);
            float nown = (n0 + n1) + (n2 + n3);
            float noth = __shfl_sync(FULL, nown, partner);

            const bool isp = lane < partner;
            float app = isp ? nown : noth;
            float aqq = isp ? noth : nown;

            maxoff = fmaxf(maxoff, __fdividef(apq * apq, app * aqq));

            float c = 1.0f, s = 0.0f;
            if (fabsf(apq) > 1e-32f) {
                float tau = __fdividef(aqq - app, 2.0f * apq);
                float t   = __fdividef(copysignf(1.0f, tau),
                                       fabsf(tau) + sqrtf(fmaf(tau, tau, 1.0f)));
                c = rsqrtf(fmaf(t, t, 1.0f));
                s = c * t;
            }
            // new a_p = c a_p - s a_q ; new a_q = s a_p + c a_q
            float ss = isp ? -s : s;
            #pragma unroll
            for (int i = 0; i < 32; i++) a[i] = fmaf(ss, b[i], c * a[i]);
        }
        // Warp-level convergence check (uniform -> no shuffle divergence).
        #pragma unroll
        for (int o = 16; o > 0; o >>= 1)
            maxoff = fmaxf(maxoff, __shfl_xor_sync(FULL, maxoff, o));
        if (maxoff < 1e-12f) break;
    }

    // ---- Finalize: lambda = ||w||, u = w/lambda, g = log(lambda) ----
    float n0=0.f,n1=0.f,n2=0.f,n3=0.f;
    #pragma unroll
    for (int i = 0; i < 32; i += 4) {
        n0 = fmaf(a[i+0], a[i+0], n0);
        n1 = fmaf(a[i+1], a[i+1], n1);
        n2 = fmaf(a[i+2], a[i+2], n2);
        n3 = fmaf(a[i+3], a[i+3], n3);
    }
    float norm = (n0 + n1) + (n2 + n3);   // = lambda^2
    float invl = rsqrtf(norm);
    float g    = 0.5f * logf(norm);       // log(lambda)

    float* su = sh[wib];          // U stored as su[row*33 + col] (stride 33: conflict-free)
    float* sg = su + 32 * 33;
    #pragma unroll
    for (int i = 0; i < 32; i++) su[i * 33 + lane] = a[i] * invl;
    sg[lane] = g;
    __syncwarp();

    // ---- X = U diag(g) U^T ; thread computes row `lane` (X symmetric) ----
    float x[32];
    #pragma unroll
    for (int rr = 0; rr < 32; rr++) x[rr] = 0.0f;
    #pragma unroll
    for (int i = 0; i < 32; i++) {
        // coef: per-lane stride-33 read (conflict-free); su[r*33+i]: broadcast.
        float coef = sg[i] * su[lane * 33 + i];
        #pragma unroll
        for (int rr = 0; rr < 32; rr++)
            x[rr] = fmaf(coef, su[rr * 33 + i], x[rr]);
    }

    // Store row `lane` of X: 8x STG.128, coalesced.
    float4* o4 = reinterpret_cast<float4*>(out + (size_t)mat * 1024 + lane * 32);
    #pragma unroll
    for (int k = 0; k < 8; k++)
        o4[k] = make_float4(x[4*k+0], x[4*k+1], x[4*k+2], x[4*k+3]);
}

extern "C" void kernel_launch(void* const* d_in, const int* in_sizes, int n_in,
                              void* d_out, int out_size)
{
    const float* P = (const float*)d_in[0];
    float* out = (float*)d_out;
    int nmat = in_sizes[0] / 1024;           // 32x32 matrices
    int blocks = (nmat + WPB - 1) / WPB;
    logeig_kernel<<<blocks, WPB * 32>>>(P, out, nmat);
}

// round 3
// speedup vs baseline: 2.3826x; 2.3826x over previous
#include <cuda_runtime.h>
#include <math.h>

#define FULL 0xffffffffu
#define WPB 4  // warps (matrices) per block

typedef unsigned long long u64;

// ---- packed fp32x2 helpers (sm_100+; ptxas never auto-fuses these) ----
__device__ __forceinline__ u64 pack2(float lo, float hi) {
    u64 r; asm("mov.b64 %0,{%1,%2};" : "=l"(r) : "f"(lo), "f"(hi)); return r;
}
__device__ __forceinline__ float2 unpack2(u64 v) {
    float2 f; asm("mov.b64 {%0,%1},%2;" : "=f"(f.x), "=f"(f.y) : "l"(v)); return f;
}
__device__ __forceinline__ u64 fma2(u64 a, u64 b, u64 c) {
    u64 d; asm("fma.rn.f32x2 %0,%1,%2,%3;" : "=l"(d) : "l"(a), "l"(b), "l"(c)); return d;
}
__device__ __forceinline__ u64 mul2(u64 a, u64 b) {
    u64 d; asm("mul.rn.f32x2 %0,%1,%2;" : "=l"(d) : "l"(a), "l"(b)); return d;
}

// One-sided (Hestenes) Jacobi, one warp per 32x32 SPD matrix, columns packed
// as 16 x f32x2. lambda_i = ||w_i||, u_i = w_i/||w_i||, X = U diag(log l) U^T.
__global__ __launch_bounds__(WPB * 32, 3)
void logeig_kernel(const float* __restrict__ P, float* __restrict__ out, int nmat)
{
    // Per-warp: sT[e*34 + r] = U[r][e] (eigenvector-major, stride 34 keeps
    // 8B alignment for packed row-pair reads; 2-way bank conflict on writes only)
    // + 32 floats of log-eigenvalues.
    __shared__ __align__(16) float sh[WPB][32 * 34 + 32];
    const int lane = threadIdx.x & 31;
    const int wib  = threadIdx.x >> 5;
    const int mat  = blockIdx.x * WPB + wib;
    if (mat >= nmat) return;

    // Load row `lane` (== column, P symmetric): 8x LDG.128 coalesced, pack pairs.
    u64 A[16];
    {
        const float4* p4 = reinterpret_cast<const float4*>(P + (size_t)mat * 1024 + lane * 32);
        #pragma unroll
        for (int k = 0; k < 8; k++) {
            float4 v = p4[k];
            A[2*k+0] = pack2(v.x, v.y);
            A[2*k+1] = pack2(v.z, v.w);
        }
    }

    // ---- Jacobi sweeps (tournament ordering, 31 rounds/sweep) ----
    for (int sweep = 0; sweep < 10; sweep++) {
        float maxoff = 0.0f;
        for (int r = 0; r < 31; r++) {
            // 1-factorization of K32: lanes i,j<31 pair iff i+j == r (mod 31);
            // lane with 2i == r (mod 31) pairs with lane 31 (16 = 2^-1 mod 31).
            int partner;
            if (lane == 31) {
                partner = (16 * r) % 31;
            } else {
                int j = r - lane; if (j < 0) j += 31;
                partner = (j == lane) ? 31 : j;
            }

            u64 B[16];
            #pragma unroll
            for (int i = 0; i < 16; i++) B[i] = __shfl_sync(FULL, A[i], partner);

            // dot(a,b) and ||a||^2, 4 packed accumulators each.
            // Identical products & reduction order on both lanes of a pair
            // -> bitwise-identical apq -> identical rotation, no extra exchange.
            u64 d0=0,d1=0,d2=0,d3=0, n0=0,n1=0,n2=0,n3=0;
            #pragma unroll
            for (int i = 0; i < 16; i += 4) {
                d0 = fma2(A[i+0], B[i+0], d0); n0 = fma2(A[i+0], A[i+0], n0);
                d1 = fma2(A[i+1], B[i+1], d1); n1 = fma2(A[i+1], A[i+1], n1);
                d2 = fma2(A[i+2], B[i+2], d2); n2 = fma2(A[i+2], A[i+2], n2);
                d3 = fma2(A[i+3], B[i+3], d3); n3 = fma2(A[i+3], A[i+3], n3);
            }
            float2 f0 = unpack2(d0), f1 = unpack2(d1), f2 = unpack2(d2), f3 = unpack2(d3);
            float apq  = ((f0.x + f0.y) + (f1.x + f1.y)) + ((f2.x + f2.y) + (f3.x + f3.y));
            float2 g0 = unpack2(n0), g1 = unpack2(n1), g2 = unpack2(n2), g3 = unpack2(n3);
            float nown = ((g0.x + g0.y) + (g1.x + g1.y)) + ((g2.x + g2.y) + (g3.x + g3.y));
            float noth = __shfl_sync(FULL, nown, partner);

            const bool isp = lane < partner;
            float app = isp ? nown : noth;
            float aqq = isp ? noth : nown;

            maxoff = fmaxf(maxoff, __fdividef(apq * apq, app * aqq));

            float c = 1.0f, s = 0.0f;
            if (fabsf(apq) > 1e-32f) {
                float tau = __fdividef(aqq - app, 2.0f * apq);
                float t   = __fdividef(copysignf(1.0f, tau),
                                       fabsf(tau) + sqrtf(fmaf(tau, tau, 1.0f)));
                c = rsqrtf(fmaf(t, t, 1.0f));
                s = c * t;
            }
            // new a_p = c a_p - s a_q ; new a_q = s a_p + c a_q
            u64 C = pack2(c, c);
            u64 S = pack2(isp ? -s : s, isp ? -s : s);
            #pragma unroll
            for (int i = 0; i < 16; i++) A[i] = fma2(S, B[i], mul2(C, A[i]));
        }
        #pragma unroll
        for (int o = 16; o > 0; o >>= 1)
            maxoff = fmaxf(maxoff, __shfl_xor_sync(FULL, maxoff, o));
        if (maxoff < 1e-12f) break;
    }

    // ---- Finalize: lambda = ||w||, u = w/lambda, g = log(lambda) ----
    u64 n0=0, n1=0, n2=0, n3=0;
    #pragma unroll
    for (int i = 0; i < 16; i += 4) {
        n0 = fma2(A[i+0], A[i+0], n0);
        n1 = fma2(A[i+1], A[i+1], n1);
        n2 = fma2(A[i+2], A[i+2], n2);
        n3 = fma2(A[i+3], A[i+3], n3);
    }
    float2 g0 = unpack2(n0), g1 = unpack2(n1), g2 = unpack2(n2), g3 = unpack2(n3);
    float norm = ((g0.x + g0.y) + (g1.x + g1.y)) + ((g2.x + g2.y) + (g3.x + g3.y)); // lambda^2
    float invl = rsqrtf(norm);
    float g    = 0.5f * logf(norm);

    float* sT = sh[wib];
    float* sg = sT + 32 * 34;
    // lane t owns eigenvector t: write its 32 rows packed (16x STS.64).
    {
        u64* dst = reinterpret_cast<u64*>(sT + lane * 34);
        u64 IV = pack2(invl, invl);
        #pragma unroll
        for (int i = 0; i < 16; i++) dst[i] = mul2(A[i], IV);
    }
    sg[lane] = g;
    __syncwarp();

    // ---- X = U diag(g) U^T ; thread computes row `lane`, cols packed in pairs ----
    u64 X[16];
    #pragma unroll
    for (int cc = 0; cc < 16; cc++) X[cc] = 0;
    #pragma unroll
    for (int i = 0; i < 32; i++) {
        float coef = sg[i] * sT[i * 34 + lane];         // conflict-free
        u64 CP = pack2(coef, coef);
        const u64* rowp = reinterpret_cast<const u64*>(sT + i * 34);  // broadcast LDS.64
        #pragma unroll
        for (int cc = 0; cc < 16; cc++)
            X[cc] = fma2(CP, rowp[cc], X[cc]);
    }

    // Store row `lane`: 8x STG.128 coalesced.
    float4* o4 = reinterpret_cast<float4*>(out + (size_t)mat * 1024 + lane * 32);
    #pragma unroll
    for (int k = 0; k < 8; k++) {
        float2 lo = unpack2(X[2*k+0]);
        float2 hi = unpack2(X[2*k+1]);
        o4[k] = make_float4(lo.x, lo.y, hi.x, hi.y);
    }
}

extern "C" void kernel_launch(void* const* d_in, const int* in_sizes, int n_in,
                              void* d_out, int out_size)
{
    const float* P = (const float*)d_in[0];
    float* out = (float*)d_out;
    int nmat = in_sizes[0] / 1024;
    int blocks = (nmat + WPB - 1) / WPB;
    logeig_kernel<<<blocks, WPB * 32>>>(P, out, nmat);
}